// round 1
// baseline (speedup 1.0000x reference)
#include <cuda_runtime.h>

// ---------------- problem constants ----------------
#define BB     32
#define TT     512
#define DD     128
#define HH     8
#define DHH    16
#define EE     8
#define DEPTH_ 4
#define FFH    512
#define NBC    55
#define NCC    8
#define INJ    440          // NBC*NCC
#define NTOK   16384        // BB*TT
#define NASG   32768        // NTOK*2

// ---------------- scratch (device globals; no allocation) ----------------
__device__ float g_h[NTOK * DD];
__device__ float g_z[NTOK * DD];
__device__ float g_qkv[NTOK * 3 * DD];
__device__ float g_o[NTOK * DD];
__device__ float g_y[NASG * DD];
__device__ float g_blockSumP[512 * EE];
__device__ int   g_count[EE];
__device__ int   g_base[EE];
__device__ int   g_cursor[EE];
__device__ int   g_tok[NASG];
__device__ int   g_tope[NTOK * 2];
__device__ float g_topw[NTOK * 2];
__device__ int   g_pos[NTOK * 2];
__device__ float g_aux[1];

// ---------------- input projection (fused transpose-gather GEMM) ----------------
// h[b*T+t, d] = sum_j x[b, j/8, t, j%8] * proj_W[j,d] + proj_b[d] + pos[t,d]
__global__ void k_proj(const float* __restrict__ x, const float* __restrict__ W,
                       const float* __restrict__ bias, const float* __restrict__ pos) {
    __shared__ float A[16 * INJ];  // 28 KB
    int t0 = blockIdx.x * 16;
    for (int idx = threadIdx.x; idx < 16 * INJ; idx += 256) {
        int i = idx / INJ, j = idx - i * INJ;
        int tok = t0 + i;
        int b = tok >> 9, t = tok & 511;
        A[idx] = x[(((b * NBC + j / NCC) * TT + t) * NCC) + (j % NCC)];
    }
    __syncthreads();
    int d = threadIdx.x & 127, g = threadIdx.x >> 7;  // 2 groups x 8 tokens
    float acc[8] = {0.f, 0.f, 0.f, 0.f, 0.f, 0.f, 0.f, 0.f};
    for (int j = 0; j < INJ; j++) {
        float w = W[j * DD + d];
#pragma unroll
        for (int i = 0; i < 8; i++) acc[i] += A[(g * 8 + i) * INJ + j] * w;
    }
    float bb = bias[d];
#pragma unroll
    for (int i = 0; i < 8; i++) {
        int tok = t0 + g * 8 + i;
        int t = tok & 511;
        g_h[tok * DD + d] = acc[i] + bb + pos[t * DD + d];
    }
}

// ---------------- LayerNorm: g_h -> g_z (warp per token) ----------------
__global__ void k_ln(const float* __restrict__ gam, const float* __restrict__ bet) {
    int warp = (blockIdx.x * blockDim.x + threadIdx.x) >> 5;
    int lane = threadIdx.x & 31;
    if (warp >= NTOK) return;
    const float* xr = g_h + warp * DD;
    float v[4];
    float s = 0.f;
#pragma unroll
    for (int j = 0; j < 4; j++) { v[j] = xr[lane + j * 32]; s += v[j]; }
#pragma unroll
    for (int o = 16; o; o >>= 1) s += __shfl_xor_sync(0xffffffffu, s, o);
    float m = s * (1.0f / DD);
    float q = 0.f;
#pragma unroll
    for (int j = 0; j < 4; j++) { float dv = v[j] - m; q += dv * dv; }
#pragma unroll
    for (int o = 16; o; o >>= 1) q += __shfl_xor_sync(0xffffffffu, q, o);
    float r = rsqrtf(q * (1.0f / DD) + 1e-5f);
#pragma unroll
    for (int j = 0; j < 4; j++) {
        int d = lane + j * 32;
        g_z[warp * DD + d] = (v[j] - m) * r * gam[d] + bet[d];
    }
}

// ---------------- qkv GEMM: g_z[16384,128] @ W[128,384] + b -> g_qkv ----------------
__global__ void k_gemm_qkv(const float* __restrict__ W, const float* __restrict__ bias) {
    __shared__ float As[32 * DD];  // 16 KB
    int t0 = blockIdx.x * 32;
    for (int idx = threadIdx.x; idx < 32 * DD; idx += 256) As[idx] = g_z[t0 * DD + idx];
    __syncthreads();
    int col = blockIdx.y * 128 + (threadIdx.x & 127);
    int g = threadIdx.x >> 7;
    float acc[16] = {};
    for (int k = 0; k < DD; k++) {
        float w = W[k * 384 + col];
#pragma unroll
        for (int i = 0; i < 16; i++) acc[i] += As[(g * 16 + i) * DD + k] * w;
    }
    float bb = bias[col];
#pragma unroll
    for (int i = 0; i < 16; i++) g_qkv[(t0 + g * 16 + i) * 384 + col] = acc[i] + bb;
}

// ---------------- attention (one block per (b,h); K,V in smem; online softmax) ----------------
__global__ void k_attn() {
    extern __shared__ float sm[];
    float* Ks = sm;
    float* Vs = sm + TT * DHH;
    int b = blockIdx.x >> 3, hh = blockIdx.x & 7;
    const float* base = g_qkv + (b * TT) * 384;
    for (int idx = threadIdx.x; idx < TT * DHH; idx += 256) {
        int k = idx >> 4, d = idx & 15;
        Ks[idx] = base[k * 384 + 128 + hh * 16 + d];
        Vs[idx] = base[k * 384 + 256 + hh * 16 + d];
    }
    __syncthreads();
#pragma unroll 1
    for (int rr = 0; rr < 2; rr++) {
        int r = threadIdx.x + rr * 256;
        float q[16];
#pragma unroll
        for (int d = 0; d < 16; d++) q[d] = base[r * 384 + hh * 16 + d];
        float m = -1e30f, l = 0.f;
        float o[16] = {};
        for (int k = 0; k < TT; k++) {
            const float* kr = Ks + k * 16;
            float s0 = q[0] * kr[0], s1 = q[1] * kr[1], s2 = q[2] * kr[2], s3 = q[3] * kr[3];
#pragma unroll
            for (int d = 4; d < 16; d += 4) {
                s0 += q[d] * kr[d]; s1 += q[d + 1] * kr[d + 1];
                s2 += q[d + 2] * kr[d + 2]; s3 += q[d + 3] * kr[d + 3];
            }
            float s = ((s0 + s1) + (s2 + s3)) * 0.25f;
            if (s > m) {
                float f = __expf(m - s);
                l *= f;
#pragma unroll
                for (int d = 0; d < 16; d++) o[d] *= f;
                m = s;
            }
            float p = __expf(s - m);
            l += p;
            const float* vr = Vs + k * 16;
#pragma unroll
            for (int d = 0; d < 16; d++) o[d] += p * vr[d];
        }
        float inv = 1.0f / l;
#pragma unroll
        for (int d = 0; d < 16; d++) g_o[(b * TT + r) * DD + hh * 16 + d] = o[d] * inv;
    }
}

// ---------------- out proj GEMM + residual: g_h += g_o @ W + b ----------------
__global__ void k_gemm_out(const float* __restrict__ W, const float* __restrict__ bias) {
    __shared__ float As[32 * DD];
    int t0 = blockIdx.x * 32;
    for (int idx = threadIdx.x; idx < 32 * DD; idx += 256) As[idx] = g_o[t0 * DD + idx];
    __syncthreads();
    int col = threadIdx.x & 127;
    int g = threadIdx.x >> 7;
    float acc[16] = {};
    for (int k = 0; k < DD; k++) {
        float w = W[k * DD + col];
#pragma unroll
        for (int i = 0; i < 16; i++) acc[i] += As[(g * 16 + i) * DD + k] * w;
    }
    float bb = bias[col];
#pragma unroll
    for (int i = 0; i < 16; i++) g_h[(t0 + g * 16 + i) * DD + col] += acc[i] + bb;
}

// ---------------- gate: logits, softmax, top-2, counts, per-block prob sums ----------------
__global__ void k_zero_gate() {
    if (threadIdx.x < EE) g_count[threadIdx.x] = 0;
}

__global__ void k_gate(const float* __restrict__ gW) {
    __shared__ float zs[32 * DD];   // 16 KB
    __shared__ float gw[DD * EE];   // 4 KB
    __shared__ float lg[32 * EE];
    __shared__ float sp[32 * EE];
    int t0 = blockIdx.x * 32;
    for (int idx = threadIdx.x; idx < 32 * DD; idx += 256) zs[idx] = g_z[t0 * DD + idx];
    for (int idx = threadIdx.x; idx < DD * EE; idx += 256) gw[idx] = gW[idx];
    __syncthreads();
    {
        int tok = threadIdx.x >> 3, e = threadIdx.x & 7;
        float acc = 0.f;
        for (int k = 0; k < DD; k++) acc += zs[tok * DD + k] * gw[k * EE + e];
        lg[tok * EE + e] = acc;
    }
    __syncthreads();
    if (threadIdx.x < 32) {
        int tt = threadIdx.x;
        float mx = -1e30f;
#pragma unroll
        for (int j = 0; j < 8; j++) mx = fmaxf(mx, lg[tt * 8 + j]);
        float p[8];
        float s = 0.f;
#pragma unroll
        for (int j = 0; j < 8; j++) { p[j] = __expf(lg[tt * 8 + j] - mx); s += p[j]; }
        float invs = 1.f / s;
#pragma unroll
        for (int j = 0; j < 8; j++) p[j] *= invs;
        // top-2 on logits (same ordering as probs, earliest index on ties -> matches lax.top_k)
        int i1 = 0; float l1 = lg[tt * 8];
        for (int j = 1; j < 8; j++) if (lg[tt * 8 + j] > l1) { l1 = lg[tt * 8 + j]; i1 = j; }
        int i2 = -1; float l2 = -1e30f;
        for (int j = 0; j < 8; j++)
            if (j != i1 && lg[tt * 8 + j] > l2) { l2 = lg[tt * 8 + j]; i2 = j; }
        float v1 = p[i1], v2 = p[i2];
        float ws = 1.f / (v1 + v2);
        int t = t0 + tt;
        g_tope[t * 2] = i1; g_tope[t * 2 + 1] = i2;
        g_topw[t * 2] = v1 * ws; g_topw[t * 2 + 1] = v2 * ws;
        atomicAdd(&g_count[i1], 1);
        atomicAdd(&g_count[i2], 1);
#pragma unroll
        for (int j = 0; j < 8; j++) sp[tt * 8 + j] = p[j];
    }
    __syncthreads();
    if (threadIdx.x < 8) {
        float s = 0.f;
        for (int tt = 0; tt < 32; tt++) s += sp[tt * 8 + threadIdx.x];
        g_blockSumP[blockIdx.x * 8 + threadIdx.x] = s;
    }
}

// ---------------- scan bases + deterministic aux accumulation ----------------
__global__ void k_scan_aux() {
    __shared__ float sump[8];
    int tid = threadIdx.x;
    if (tid < 8) {
        float s = 0.f;
        for (int b = 0; b < 512; b++) s += g_blockSumP[b * 8 + tid];
        sump[tid] = s;
    }
    __syncthreads();
    if (tid == 0) {
        int off = 0;
        float a = 0.f;
        for (int e = 0; e < 8; e++) {
            g_base[e] = off;
            g_cursor[e] = off;
            off += g_count[e];
            a += sump[e] * (float)g_count[e];
        }
        g_aux[0] += 8.0f * a / (16384.f * 16384.f);
    }
}

// ---------------- assignment (block-aggregated atomics) ----------------
__global__ void k_assign() {
    __shared__ int cnt[8], gbase[8];
    int tid = threadIdx.x;
    if (tid < 8) cnt[tid] = 0;
    __syncthreads();
    int t = blockIdx.x * 256 + tid;
    int e0 = g_tope[t * 2], e1 = g_tope[t * 2 + 1];
    int o0 = atomicAdd(&cnt[e0], 1);
    int o1 = atomicAdd(&cnt[e1], 1);
    __syncthreads();
    if (tid < 8) gbase[tid] = atomicAdd(&g_cursor[tid], cnt[tid]);
    __syncthreads();
    int p0 = gbase[e0] + o0, p1 = gbase[e1] + o1;
    g_tok[p0] = t; g_tok[p1] = t;
    g_pos[t * 2] = p0; g_pos[t * 2 + 1] = p1;
}

// ---------------- grouped expert FFN: y = w2^T gelu(z w1 + b1) + b2 ----------------
__global__ void k_ffn(const float* __restrict__ w1, const float* __restrict__ b1,
                      const float* __restrict__ w2, const float* __restrict__ b2) {
    int e = blockIdx.y;
    int n = g_count[e];
    int start = blockIdx.x * 32;
    if (start >= n) return;
    int base = g_base[e];
    extern __shared__ float sm[];
    float* zs = sm;            // 32*128
    float* hid = sm + 32 * DD; // 32*512
    __shared__ int toks[32];
    int tid = threadIdx.x;
    if (tid < 32) toks[tid] = (start + tid < n) ? g_tok[base + start + tid] : -1;
    __syncthreads();
    for (int idx = tid; idx < 32 * DD; idx += 256) {
        int i = idx >> 7;
        int tk = toks[i];
        zs[idx] = (tk >= 0) ? g_z[tk * DD + (idx & 127)] : 0.f;
    }
    __syncthreads();
    const float* W1 = w1 + e * DD * FFH;
    const float* B1 = b1 + e * FFH;
#pragma unroll 1
    for (int pp = 0; pp < 2; pp++) {
        int f = pp * 256 + tid;
        float acc[32] = {};
        for (int d = 0; d < DD; d++) {
            float w = W1[d * FFH + f];
#pragma unroll
            for (int i = 0; i < 32; i++) acc[i] += zs[i * DD + d] * w;
        }
        float bb = B1[f];
#pragma unroll 4
        for (int i = 0; i < 32; i++) {
            float x = acc[i] + bb;
            float t = tanhf(0.7978845608028654f * (x + 0.044715f * x * x * x));
            hid[i * FFH + f] = 0.5f * x * (1.f + t);
        }
    }
    __syncthreads();
    const float* W2 = w2 + e * FFH * DD;
    const float* B2 = b2 + e * DD;
    int d = tid & 127, g = tid >> 7;
    float acc2[16] = {};
    for (int f = 0; f < FFH; f++) {
        float w = W2[f * DD + d];
#pragma unroll
        for (int i = 0; i < 16; i++) acc2[i] += hid[(g * 16 + i) * FFH + f] * w;
    }
    float bb = B2[d];
#pragma unroll
    for (int i = 0; i < 16; i++) {
        int a = start + g * 16 + i;
        if (a < n) g_y[(base + a) * DD + d] = acc2[i] + bb;
    }
}

// ---------------- combine: h += w0*y[pos0] + w1*y[pos1] ----------------
__global__ void k_combine() {
    int idx = blockIdx.x * 256 + threadIdx.x;
    int t = idx >> 7, d = idx & 127;
    float w0 = g_topw[t * 2], w1v = g_topw[t * 2 + 1];
    int p0 = g_pos[t * 2], p1 = g_pos[t * 2 + 1];
    g_h[idx] += w0 * g_y[p0 * DD + d] + w1v * g_y[p1 * DD + d];
}

// ---------------- head: mean-pool, LN, [128,2] GEMV, aux writeout ----------------
__global__ void k_head(const float* __restrict__ lng, const float* __restrict__ lnb,
                       const float* __restrict__ hW, const float* __restrict__ hb,
                       float* __restrict__ out, int out_size) {
    __shared__ float red[128];
    int b = blockIdx.x, d = threadIdx.x;
    float s = 0.f;
    for (int t = 0; t < TT; t++) s += g_h[(b * TT + t) * DD + d];
    float x = s * (1.f / TT);
    red[d] = x;
    __syncthreads();
    for (int o = 64; o; o >>= 1) { if (d < o) red[d] += red[d + o]; __syncthreads(); }
    float m = red[0] * (1.f / DD);
    __syncthreads();
    float dv = x - m;
    red[d] = dv * dv;
    __syncthreads();
    for (int o = 64; o; o >>= 1) { if (d < o) red[d] += red[d + o]; __syncthreads(); }
    float var = red[0] * (1.f / DD);
    __syncthreads();
    float p = dv * rsqrtf(var + 1e-5f) * lng[d] + lnb[d];
#pragma unroll 1
    for (int j = 0; j < 2; j++) {
        red[d] = p * hW[d * 2 + j];
        __syncthreads();
        for (int o = 64; o; o >>= 1) { if (d < o) red[d] += red[d + o]; __syncthreads(); }
        if (d == 0) out[b * 2 + j] = red[0] + hb[j];
        __syncthreads();
    }
    if (b == 0 && d == 0 && out_size > 64) out[64] = g_aux[0];
}

__global__ void k_zero_aux() {
    if (threadIdx.x == 0) g_aux[0] = 0.f;
}

// ---------------- host launch ----------------
extern "C" void kernel_launch(void* const* d_in, const int* in_sizes, int n_in,
                              void* d_out, int out_size) {
    const float* x     = (const float*)d_in[0];
    const float* projW = (const float*)d_in[1];
    const float* projb = (const float*)d_in[2];
    const float* pos   = (const float*)d_in[3];
    const float* ln1g  = (const float*)d_in[4];
    const float* ln1b  = (const float*)d_in[5];
    const float* qkvW  = (const float*)d_in[6];
    const float* qkvb  = (const float*)d_in[7];
    const float* outW  = (const float*)d_in[8];
    const float* outb  = (const float*)d_in[9];
    const float* ln2g  = (const float*)d_in[10];
    const float* ln2b  = (const float*)d_in[11];
    const float* gateW = (const float*)d_in[12];
    const float* w1    = (const float*)d_in[13];
    const float* b1    = (const float*)d_in[14];
    const float* w2    = (const float*)d_in[15];
    const float* b2    = (const float*)d_in[16];
    const float* hlng  = (const float*)d_in[17];
    const float* hlnb  = (const float*)d_in[18];
    const float* hW    = (const float*)d_in[19];
    const float* hb    = (const float*)d_in[20];
    float* out = (float*)d_out;

    cudaFuncSetAttribute(k_attn, cudaFuncAttributeMaxDynamicSharedMemorySize, 65536);
    cudaFuncSetAttribute(k_ffn, cudaFuncAttributeMaxDynamicSharedMemorySize, 81920);

    k_zero_aux<<<1, 32>>>();
    k_proj<<<NTOK / 16, 256>>>(x, projW, projb, pos);

    for (int i = 0; i < DEPTH_; i++) {
        k_ln<<<NTOK / 8, 256>>>(ln1g + i * DD, ln1b + i * DD);
        k_gemm_qkv<<<dim3(NTOK / 32, 3), 256>>>(qkvW + i * DD * 384, qkvb + i * 384);
        k_attn<<<BB * HH, 256, 65536>>>();
        k_gemm_out<<<NTOK / 32, 256>>>(outW + i * DD * DD, outb + i * DD);
        k_ln<<<NTOK / 8, 256>>>(ln2g + i * DD, ln2b + i * DD);
        k_zero_gate<<<1, 32>>>();
        k_gate<<<NTOK / 32, 256>>>(gateW + i * DD * EE);
        k_scan_aux<<<1, 32>>>();
        k_assign<<<NTOK / 256, 256>>>();
        k_ffn<<<dim3(NASG / 32, EE), 256, 81920>>>(w1 + i * EE * DD * FFH, b1 + i * EE * FFH,
                                                   w2 + i * EE * FFH * DD, b2 + i * EE * DD);
        k_combine<<<NTOK * DD / 256, 256>>>();
    }

    k_head<<<BB, 128>>>(hlng, hlnb, hW, hb, out, out_size);
}

// round 2
// speedup vs baseline: 1.6398x; 1.6398x over previous
#include <cuda_runtime.h>

// ---------------- problem constants ----------------
#define BB     32
#define TT     512
#define DD     128
#define HH     8
#define DHH    16
#define EE     8
#define DEPTH_ 4
#define FFH    512
#define NBC    55
#define NCC    8
#define INJ    440          // NBC*NCC
#define NTOK   16384        // BB*TT
#define NASG   32768        // NTOK*2
#define PAD    36           // padded row stride (floats) for transposed tiles

// ---------------- scratch (device globals; no allocation) ----------------
__device__ float g_h[NTOK * DD];
__device__ float g_z[NTOK * DD];
__device__ float g_qkv[NTOK * 3 * DD];
__device__ float g_o[NTOK * DD];
__device__ float g_y[NASG * DD];
__device__ float g_blockSumP[512 * EE];
__device__ int   g_count[EE];
__device__ int   g_base[EE];
__device__ int   g_cursor[EE];
__device__ int   g_tok[NASG];
__device__ int   g_tope[NTOK * 2];
__device__ float g_topw[NTOK * 2];
__device__ int   g_pos[NTOK * 2];
__device__ float g_aux[1];

#define FMA16(acc, a4, w)                                        \
    do {                                                         \
        acc[0] = fmaf(a4[0].x, w, acc[0]);                       \
        acc[1] = fmaf(a4[0].y, w, acc[1]);                       \
        acc[2] = fmaf(a4[0].z, w, acc[2]);                       \
        acc[3] = fmaf(a4[0].w, w, acc[3]);                       \
        acc[4] = fmaf(a4[1].x, w, acc[4]);                       \
        acc[5] = fmaf(a4[1].y, w, acc[5]);                       \
        acc[6] = fmaf(a4[1].z, w, acc[6]);                       \
        acc[7] = fmaf(a4[1].w, w, acc[7]);                       \
        acc[8] = fmaf(a4[2].x, w, acc[8]);                       \
        acc[9] = fmaf(a4[2].y, w, acc[9]);                       \
        acc[10] = fmaf(a4[2].z, w, acc[10]);                     \
        acc[11] = fmaf(a4[2].w, w, acc[11]);                     \
        acc[12] = fmaf(a4[3].x, w, acc[12]);                     \
        acc[13] = fmaf(a4[3].y, w, acc[13]);                     \
        acc[14] = fmaf(a4[3].z, w, acc[14]);                     \
        acc[15] = fmaf(a4[3].w, w, acc[15]);                     \
    } while (0)

// ---------------- input projection (transposed-smem GEMM, 32-token tiles) ----------------
__global__ void k_proj(const float* __restrict__ x, const float* __restrict__ W,
                       const float* __restrict__ bias, const float* __restrict__ pos) {
    extern __shared__ float AsT[];  // [INJ][PAD] = 63360 B
    int t0 = blockIdx.x * 32;
    for (int idx = threadIdx.x; idx < 32 * INJ; idx += 256) {
        int i = idx / INJ, j = idx - i * INJ;
        int tok = t0 + i;
        int b = tok >> 9, t = tok & 511;
        AsT[j * PAD + i] = x[(((b * NBC + j / NCC) * TT + t) * NCC) + (j % NCC)];
    }
    __syncthreads();
    int d = threadIdx.x & 127, g = threadIdx.x >> 7;
    float acc[16] = {};
    float4 a4[4];
#pragma unroll 4
    for (int j = 0; j < INJ; j++) {
        float w = W[j * DD + d];
        const float4* ap = (const float4*)(AsT + j * PAD + g * 16);
        a4[0] = ap[0]; a4[1] = ap[1]; a4[2] = ap[2]; a4[3] = ap[3];
        FMA16(acc, a4, w);
    }
    float bb = bias[d];
#pragma unroll
    for (int i = 0; i < 16; i++) {
        int tok = t0 + g * 16 + i;
        int t = tok & 511;
        g_h[tok * DD + d] = acc[i] + bb + pos[t * DD + d];
    }
}

// ---------------- LayerNorm: g_h -> g_z (warp per token) ----------------
__global__ void k_ln(const float* __restrict__ gam, const float* __restrict__ bet) {
    int warp = (blockIdx.x * blockDim.x + threadIdx.x) >> 5;
    int lane = threadIdx.x & 31;
    if (warp >= NTOK) return;
    const float* xr = g_h + warp * DD;
    float v[4];
    float s = 0.f;
#pragma unroll
    for (int j = 0; j < 4; j++) { v[j] = xr[lane + j * 32]; s += v[j]; }
#pragma unroll
    for (int o = 16; o; o >>= 1) s += __shfl_xor_sync(0xffffffffu, s, o);
    float m = s * (1.0f / DD);
    float q = 0.f;
#pragma unroll
    for (int j = 0; j < 4; j++) { float dv = v[j] - m; q += dv * dv; }
#pragma unroll
    for (int o = 16; o; o >>= 1) q += __shfl_xor_sync(0xffffffffu, q, o);
    float r = rsqrtf(q * (1.0f / DD) + 1e-5f);
#pragma unroll
    for (int j = 0; j < 4; j++) {
        int d = lane + j * 32;
        g_z[warp * DD + d] = (v[j] - m) * r * gam[d] + bet[d];
    }
}

// ---------------- qkv GEMM: g_z[16384,128] @ W[128,384] + b -> g_qkv ----------------
__global__ void k_gemm_qkv(const float* __restrict__ W, const float* __restrict__ bias) {
    __shared__ float AsT[DD * PAD];  // [k][i] transposed, 18 KB
    int t0 = blockIdx.x * 32;
    for (int idx = threadIdx.x; idx < 32 * DD; idx += 256) {
        int i = idx >> 7, d = idx & 127;
        AsT[d * PAD + i] = g_z[(t0 + i) * DD + d];
    }
    __syncthreads();
    int col = blockIdx.y * 128 + (threadIdx.x & 127);
    int g = threadIdx.x >> 7;
    float acc[16] = {};
    float4 a4[4];
#pragma unroll 4
    for (int k = 0; k < DD; k++) {
        float w = W[k * 384 + col];
        const float4* ap = (const float4*)(AsT + k * PAD + g * 16);
        a4[0] = ap[0]; a4[1] = ap[1]; a4[2] = ap[2]; a4[3] = ap[3];
        FMA16(acc, a4, w);
    }
    float bb = bias[col];
#pragma unroll
    for (int i = 0; i < 16; i++) g_qkv[(t0 + g * 16 + i) * 384 + col] = acc[i] + bb;
}

// ---------------- attention (one block per (b,h); K,V in smem; online softmax) ----------------
__global__ void k_attn() {
    extern __shared__ float sm[];
    float* Ks = sm;
    float* Vs = sm + TT * DHH;
    int b = blockIdx.x >> 3, hh = blockIdx.x & 7;
    const float* base = g_qkv + (b * TT) * 384;
    for (int idx = threadIdx.x; idx < TT * DHH; idx += 256) {
        int k = idx >> 4, d = idx & 15;
        Ks[idx] = base[k * 384 + 128 + hh * 16 + d];
        Vs[idx] = base[k * 384 + 256 + hh * 16 + d];
    }
    __syncthreads();
#pragma unroll 1
    for (int rr = 0; rr < 2; rr++) {
        int r = threadIdx.x + rr * 256;
        const float4* qp = (const float4*)(base + r * 384 + hh * 16);
        float4 q0 = qp[0], q1 = qp[1], q2 = qp[2], q3 = qp[3];
        // pre-scale q by 1/sqrt(dh) = 0.25
        q0.x *= .25f; q0.y *= .25f; q0.z *= .25f; q0.w *= .25f;
        q1.x *= .25f; q1.y *= .25f; q1.z *= .25f; q1.w *= .25f;
        q2.x *= .25f; q2.y *= .25f; q2.z *= .25f; q2.w *= .25f;
        q3.x *= .25f; q3.y *= .25f; q3.z *= .25f; q3.w *= .25f;
        float m = -1e30f, l = 0.f;
        float4 o0 = {0, 0, 0, 0}, o1 = {0, 0, 0, 0}, o2 = {0, 0, 0, 0}, o3 = {0, 0, 0, 0};
        const float4* Ks4 = (const float4*)Ks;
        const float4* Vs4 = (const float4*)Vs;
        for (int k = 0; k < TT; k++) {
            float4 k0 = Ks4[k * 4], k1 = Ks4[k * 4 + 1], k2 = Ks4[k * 4 + 2], k3 = Ks4[k * 4 + 3];
            float s0 = q0.x * k0.x + q0.y * k0.y + q0.z * k0.z + q0.w * k0.w;
            float s1 = q1.x * k1.x + q1.y * k1.y + q1.z * k1.z + q1.w * k1.w;
            float s2 = q2.x * k2.x + q2.y * k2.y + q2.z * k2.z + q2.w * k2.w;
            float s3 = q3.x * k3.x + q3.y * k3.y + q3.z * k3.z + q3.w * k3.w;
            float s = (s0 + s1) + (s2 + s3);
            if (s > m) {
                float f = __expf(m - s);
                l *= f;
                o0.x *= f; o0.y *= f; o0.z *= f; o0.w *= f;
                o1.x *= f; o1.y *= f; o1.z *= f; o1.w *= f;
                o2.x *= f; o2.y *= f; o2.z *= f; o2.w *= f;
                o3.x *= f; o3.y *= f; o3.z *= f; o3.w *= f;
                m = s;
            }
            float p = __expf(s - m);
            l += p;
            float4 v0 = Vs4[k * 4], v1 = Vs4[k * 4 + 1], v2 = Vs4[k * 4 + 2], v3 = Vs4[k * 4 + 3];
            o0.x = fmaf(p, v0.x, o0.x); o0.y = fmaf(p, v0.y, o0.y);
            o0.z = fmaf(p, v0.z, o0.z); o0.w = fmaf(p, v0.w, o0.w);
            o1.x = fmaf(p, v1.x, o1.x); o1.y = fmaf(p, v1.y, o1.y);
            o1.z = fmaf(p, v1.z, o1.z); o1.w = fmaf(p, v1.w, o1.w);
            o2.x = fmaf(p, v2.x, o2.x); o2.y = fmaf(p, v2.y, o2.y);
            o2.z = fmaf(p, v2.z, o2.z); o2.w = fmaf(p, v2.w, o2.w);
            o3.x = fmaf(p, v3.x, o3.x); o3.y = fmaf(p, v3.y, o3.y);
            o3.z = fmaf(p, v3.z, o3.z); o3.w = fmaf(p, v3.w, o3.w);
        }
        float inv = 1.0f / l;
        o0.x *= inv; o0.y *= inv; o0.z *= inv; o0.w *= inv;
        o1.x *= inv; o1.y *= inv; o1.z *= inv; o1.w *= inv;
        o2.x *= inv; o2.y *= inv; o2.z *= inv; o2.w *= inv;
        o3.x *= inv; o3.y *= inv; o3.z *= inv; o3.w *= inv;
        float4* op = (float4*)(g_o + (b * TT + r) * DD + hh * 16);
        op[0] = o0; op[1] = o1; op[2] = o2; op[3] = o3;
    }
}

// ---------------- out proj GEMM + residual: g_h += g_o @ W + b ----------------
__global__ void k_gemm_out(const float* __restrict__ W, const float* __restrict__ bias) {
    __shared__ float AsT[DD * PAD];
    int t0 = blockIdx.x * 32;
    for (int idx = threadIdx.x; idx < 32 * DD; idx += 256) {
        int i = idx >> 7, d = idx & 127;
        AsT[d * PAD + i] = g_o[(t0 + i) * DD + d];
    }
    __syncthreads();
    int col = threadIdx.x & 127;
    int g = threadIdx.x >> 7;
    float acc[16] = {};
    float4 a4[4];
#pragma unroll 4
    for (int k = 0; k < DD; k++) {
        float w = W[k * DD + col];
        const float4* ap = (const float4*)(AsT + k * PAD + g * 16);
        a4[0] = ap[0]; a4[1] = ap[1]; a4[2] = ap[2]; a4[3] = ap[3];
        FMA16(acc, a4, w);
    }
    float bb = bias[col];
#pragma unroll
    for (int i = 0; i < 16; i++) g_h[(t0 + g * 16 + i) * DD + col] += acc[i] + bb;
}

// ---------------- gate: logits, softmax, top-2, counts, per-block prob sums ----------------
__global__ void k_zero_gate() {
    if (threadIdx.x < EE) g_count[threadIdx.x] = 0;
}

__global__ void k_gate(const float* __restrict__ gW) {
    __shared__ float zs[32 * DD];
    __shared__ float gw[DD * EE];
    __shared__ float lg[32 * EE];
    __shared__ float sp[32 * EE];
    int t0 = blockIdx.x * 32;
    for (int idx = threadIdx.x; idx < 32 * DD; idx += 256) zs[idx] = g_z[t0 * DD + idx];
    for (int idx = threadIdx.x; idx < DD * EE; idx += 256) gw[idx] = gW[idx];
    __syncthreads();
    {
        int tok = threadIdx.x >> 3, e = threadIdx.x & 7;
        float acc = 0.f;
        for (int k = 0; k < DD; k++) acc += zs[tok * DD + k] * gw[k * EE + e];
        lg[tok * EE + e] = acc;
    }
    __syncthreads();
    if (threadIdx.x < 32) {
        int tt = threadIdx.x;
        float mx = -1e30f;
#pragma unroll
        for (int j = 0; j < 8; j++) mx = fmaxf(mx, lg[tt * 8 + j]);
        float p[8];
        float s = 0.f;
#pragma unroll
        for (int j = 0; j < 8; j++) { p[j] = __expf(lg[tt * 8 + j] - mx); s += p[j]; }
        float invs = 1.f / s;
#pragma unroll
        for (int j = 0; j < 8; j++) p[j] *= invs;
        int i1 = 0; float l1 = lg[tt * 8];
        for (int j = 1; j < 8; j++) if (lg[tt * 8 + j] > l1) { l1 = lg[tt * 8 + j]; i1 = j; }
        int i2 = -1; float l2 = -1e30f;
        for (int j = 0; j < 8; j++)
            if (j != i1 && lg[tt * 8 + j] > l2) { l2 = lg[tt * 8 + j]; i2 = j; }
        float v1 = p[i1], v2 = p[i2];
        float ws = 1.f / (v1 + v2);
        int t = t0 + tt;
        g_tope[t * 2] = i1; g_tope[t * 2 + 1] = i2;
        g_topw[t * 2] = v1 * ws; g_topw[t * 2 + 1] = v2 * ws;
        atomicAdd(&g_count[i1], 1);
        atomicAdd(&g_count[i2], 1);
#pragma unroll
        for (int j = 0; j < 8; j++) sp[tt * 8 + j] = p[j];
    }
    __syncthreads();
    if (threadIdx.x < 8) {
        float s = 0.f;
        for (int tt = 0; tt < 32; tt++) s += sp[tt * 8 + threadIdx.x];
        g_blockSumP[blockIdx.x * 8 + threadIdx.x] = s;
    }
}

// ---------------- scan bases + deterministic aux accumulation ----------------
__global__ void k_scan_aux() {
    __shared__ float sump[8];
    int tid = threadIdx.x;
    if (tid < 8) {
        float s = 0.f;
        for (int b = 0; b < 512; b++) s += g_blockSumP[b * 8 + tid];
        sump[tid] = s;
    }
    __syncthreads();
    if (tid == 0) {
        int off = 0;
        float a = 0.f;
        for (int e = 0; e < 8; e++) {
            g_base[e] = off;
            g_cursor[e] = off;
            off += g_count[e];
            a += sump[e] * (float)g_count[e];
        }
        g_aux[0] += 8.0f * a / (16384.f * 16384.f);
    }
}

// ---------------- assignment (block-aggregated atomics) ----------------
__global__ void k_assign() {
    __shared__ int cnt[8], gbase[8];
    int tid = threadIdx.x;
    if (tid < 8) cnt[tid] = 0;
    __syncthreads();
    int t = blockIdx.x * 256 + tid;
    int e0 = g_tope[t * 2], e1 = g_tope[t * 2 + 1];
    int o0 = atomicAdd(&cnt[e0], 1);
    int o1 = atomicAdd(&cnt[e1], 1);
    __syncthreads();
    if (tid < 8) gbase[tid] = atomicAdd(&g_cursor[tid], cnt[tid]);
    __syncthreads();
    int p0 = gbase[e0] + o0, p1 = gbase[e1] + o1;
    g_tok[p0] = t; g_tok[p1] = t;
    g_pos[t * 2] = p0; g_pos[t * 2 + 1] = p1;
}

// ---------------- grouped expert FFN: y = w2^T gelu(z w1 + b1) + b2 ----------------
__global__ void k_ffn(const float* __restrict__ w1, const float* __restrict__ b1,
                      const float* __restrict__ w2, const float* __restrict__ b2) {
    int e = blockIdx.y;
    int n = g_count[e];
    int start = blockIdx.x * 32;
    if (start >= n) return;
    int base = g_base[e];
    extern __shared__ float sm[];
    float* zsT = sm;                 // [128][PAD] = 18432 B
    float* hidT = sm + DD * PAD;     // [512][PAD] = 73728 B
    __shared__ int toks[32];
    int tid = threadIdx.x;
    if (tid < 32) toks[tid] = (start + tid < n) ? g_tok[base + start + tid] : -1;
    __syncthreads();
    for (int idx = tid; idx < 32 * DD; idx += 256) {
        int i = idx >> 7, d = idx & 127;
        int tk = toks[i];
        zsT[d * PAD + i] = (tk >= 0) ? g_z[tk * DD + d] : 0.f;
    }
    __syncthreads();
    const float* W1 = w1 + e * DD * FFH;
    const float* B1 = b1 + e * FFH;
#pragma unroll 1
    for (int pp = 0; pp < 2; pp++) {
        int f = pp * 256 + tid;
        float acc[32] = {};
#pragma unroll 2
        for (int d = 0; d < DD; d++) {
            float w = W1[d * FFH + f];
            const float4* ap = (const float4*)(zsT + d * PAD);
            float4 a0 = ap[0], a1 = ap[1], a2 = ap[2], a3 = ap[3];
            float4 a4 = ap[4], a5 = ap[5], a6 = ap[6], a7 = ap[7];
            acc[0] = fmaf(a0.x, w, acc[0]);   acc[1] = fmaf(a0.y, w, acc[1]);
            acc[2] = fmaf(a0.z, w, acc[2]);   acc[3] = fmaf(a0.w, w, acc[3]);
            acc[4] = fmaf(a1.x, w, acc[4]);   acc[5] = fmaf(a1.y, w, acc[5]);
            acc[6] = fmaf(a1.z, w, acc[6]);   acc[7] = fmaf(a1.w, w, acc[7]);
            acc[8] = fmaf(a2.x, w, acc[8]);   acc[9] = fmaf(a2.y, w, acc[9]);
            acc[10] = fmaf(a2.z, w, acc[10]); acc[11] = fmaf(a2.w, w, acc[11]);
            acc[12] = fmaf(a3.x, w, acc[12]); acc[13] = fmaf(a3.y, w, acc[13]);
            acc[14] = fmaf(a3.z, w, acc[14]); acc[15] = fmaf(a3.w, w, acc[15]);
            acc[16] = fmaf(a4.x, w, acc[16]); acc[17] = fmaf(a4.y, w, acc[17]);
            acc[18] = fmaf(a4.z, w, acc[18]); acc[19] = fmaf(a4.w, w, acc[19]);
            acc[20] = fmaf(a5.x, w, acc[20]); acc[21] = fmaf(a5.y, w, acc[21]);
            acc[22] = fmaf(a5.z, w, acc[22]); acc[23] = fmaf(a5.w, w, acc[23]);
            acc[24] = fmaf(a6.x, w, acc[24]); acc[25] = fmaf(a6.y, w, acc[25]);
            acc[26] = fmaf(a6.z, w, acc[26]); acc[27] = fmaf(a6.w, w, acc[27]);
            acc[28] = fmaf(a7.x, w, acc[28]); acc[29] = fmaf(a7.y, w, acc[29]);
            acc[30] = fmaf(a7.z, w, acc[30]); acc[31] = fmaf(a7.w, w, acc[31]);
        }
        float bb = B1[f];
        float vals[32];
#pragma unroll 4
        for (int i = 0; i < 32; i++) {
            float x = acc[i] + bb;
            float t = tanhf(0.7978845608028654f * (x + 0.044715f * x * x * x));
            vals[i] = 0.5f * x * (1.f + t);
        }
        float4* hp = (float4*)(hidT + f * PAD);
#pragma unroll
        for (int i = 0; i < 8; i++)
            hp[i] = make_float4(vals[i * 4], vals[i * 4 + 1], vals[i * 4 + 2], vals[i * 4 + 3]);
    }
    __syncthreads();
    const float* W2 = w2 + e * FFH * DD;
    const float* B2 = b2 + e * DD;
    int d = tid & 127, g = tid >> 7;
    float acc2[16] = {};
    float4 a4[4];
#pragma unroll 4
    for (int f = 0; f < FFH; f++) {
        float w = W2[f * DD + d];
        const float4* hp = (const float4*)(hidT + f * PAD + g * 16);
        a4[0] = hp[0]; a4[1] = hp[1]; a4[2] = hp[2]; a4[3] = hp[3];
        FMA16(acc2, a4, w);
    }
    float bb = B2[d];
#pragma unroll
    for (int i = 0; i < 16; i++) {
        int a = start + g * 16 + i;
        if (a < n) g_y[(base + a) * DD + d] = acc2[i] + bb;
    }
}

// ---------------- combine: h += w0*y[pos0] + w1*y[pos1] ----------------
__global__ void k_combine() {
    int idx = blockIdx.x * 256 + threadIdx.x;
    int t = idx >> 7, d = idx & 127;
    float w0 = g_topw[t * 2], w1v = g_topw[t * 2 + 1];
    int p0 = g_pos[t * 2], p1 = g_pos[t * 2 + 1];
    g_h[idx] += w0 * g_y[p0 * DD + d] + w1v * g_y[p1 * DD + d];
}

// ---------------- head: mean-pool, LN, [128,2] GEMV, aux writeout ----------------
__global__ void k_head(const float* __restrict__ lng, const float* __restrict__ lnb,
                       const float* __restrict__ hW, const float* __restrict__ hb,
                       float* __restrict__ out, int out_size) {
    __shared__ float red[128];
    int b = blockIdx.x, d = threadIdx.x;
    float s = 0.f;
    for (int t = 0; t < TT; t++) s += g_h[(b * TT + t) * DD + d];
    float x = s * (1.f / TT);
    red[d] = x;
    __syncthreads();
    for (int o = 64; o; o >>= 1) { if (d < o) red[d] += red[d + o]; __syncthreads(); }
    float m = red[0] * (1.f / DD);
    __syncthreads();
    float dv = x - m;
    red[d] = dv * dv;
    __syncthreads();
    for (int o = 64; o; o >>= 1) { if (d < o) red[d] += red[d + o]; __syncthreads(); }
    float var = red[0] * (1.f / DD);
    __syncthreads();
    float p = dv * rsqrtf(var + 1e-5f) * lng[d] + lnb[d];
#pragma unroll 1
    for (int j = 0; j < 2; j++) {
        red[d] = p * hW[d * 2 + j];
        __syncthreads();
        for (int o = 64; o; o >>= 1) { if (d < o) red[d] += red[d + o]; __syncthreads(); }
        if (d == 0) out[b * 2 + j] = red[0] + hb[j];
        __syncthreads();
    }
    if (b == 0 && d == 0 && out_size > 64) out[64] = g_aux[0];
}

__global__ void k_zero_aux() {
    if (threadIdx.x == 0) g_aux[0] = 0.f;
}

// ---------------- host launch ----------------
extern "C" void kernel_launch(void* const* d_in, const int* in_sizes, int n_in,
                              void* d_out, int out_size) {
    const float* x     = (const float*)d_in[0];
    const float* projW = (const float*)d_in[1];
    const float* projb = (const float*)d_in[2];
    const float* pos   = (const float*)d_in[3];
    const float* ln1g  = (const float*)d_in[4];
    const float* ln1b  = (const float*)d_in[5];
    const float* qkvW  = (const float*)d_in[6];
    const float* qkvb  = (const float*)d_in[7];
    const float* outW  = (const float*)d_in[8];
    const float* outb  = (const float*)d_in[9];
    const float* ln2g  = (const float*)d_in[10];
    const float* ln2b  = (const float*)d_in[11];
    const float* gateW = (const float*)d_in[12];
    const float* w1    = (const float*)d_in[13];
    const float* b1    = (const float*)d_in[14];
    const float* w2    = (const float*)d_in[15];
    const float* b2    = (const float*)d_in[16];
    const float* hlng  = (const float*)d_in[17];
    const float* hlnb  = (const float*)d_in[18];
    const float* hW    = (const float*)d_in[19];
    const float* hb    = (const float*)d_in[20];
    float* out = (float*)d_out;

    cudaFuncSetAttribute(k_attn, cudaFuncAttributeMaxDynamicSharedMemorySize, 65536);
    cudaFuncSetAttribute(k_ffn, cudaFuncAttributeMaxDynamicSharedMemorySize,
                         (DD + FFH) * PAD * 4);
    cudaFuncSetAttribute(k_proj, cudaFuncAttributeMaxDynamicSharedMemorySize, INJ * PAD * 4);

    k_zero_aux<<<1, 32>>>();
    k_proj<<<NTOK / 32, 256, INJ * PAD * 4>>>(x, projW, projb, pos);

    for (int i = 0; i < DEPTH_; i++) {
        k_ln<<<NTOK / 8, 256>>>(ln1g + i * DD, ln1b + i * DD);
        k_gemm_qkv<<<dim3(NTOK / 32, 3), 256>>>(qkvW + i * DD * 384, qkvb + i * 384);
        k_attn<<<BB * HH, 256, 65536>>>();
        k_gemm_out<<<NTOK / 32, 256>>>(outW + i * DD * DD, outb + i * DD);
        k_ln<<<NTOK / 8, 256>>>(ln2g + i * DD, ln2b + i * DD);
        k_zero_gate<<<1, 32>>>();
        k_gate<<<NTOK / 32, 256>>>(gateW + i * DD * EE);
        k_scan_aux<<<1, 32>>>();
        k_assign<<<NTOK / 256, 256>>>();
        k_ffn<<<dim3(NASG / 32, EE), 256, (DD + FFH) * PAD * 4>>>(
            w1 + i * EE * DD * FFH, b1 + i * EE * FFH,
            w2 + i * EE * FFH * DD, b2 + i * EE * DD);
        k_combine<<<NTOK * DD / 256, 256>>>();
    }

    k_head<<<BB, 128>>>(hlng, hlnb, hW, hb, out, out_size);
}

// round 3
// speedup vs baseline: 1.9355x; 1.1803x over previous
#include <cuda_runtime.h>

// ---------------- problem constants ----------------
#define BB     32
#define TT     512
#define DD     128
#define HH     8
#define DHH    16
#define EE     8
#define DEPTH_ 4
#define FFH    512
#define NBC    55
#define NCC    8
#define INJ    440          // NBC*NCC
#define NTOK   16384        // BB*TT
#define NASG   32768        // NTOK*2

typedef unsigned long long u64;

// ---------------- packed f32x2 helpers ----------------
__device__ __forceinline__ u64 pk2(float x) {
    u64 r; asm("mov.b64 %0,{%1,%1};" : "=l"(r) : "f"(x)); return r;
}
__device__ __forceinline__ float2 up2(u64 a) {
    float2 r; asm("mov.b64 {%0,%1},%2;" : "=f"(r.x), "=f"(r.y) : "l"(a)); return r;
}
__device__ __forceinline__ u64 fma2(u64 a, u64 b, u64 c) {
    u64 d; asm("fma.rn.f32x2 %0,%1,%2,%3;" : "=l"(d) : "l"(a), "l"(b), "l"(c)); return d;
}
__device__ __forceinline__ u64 mul2(u64 a, u64 b) {
    u64 d; asm("mul.rn.f32x2 %0,%1,%2;" : "=l"(d) : "l"(a), "l"(b)); return d;
}
__device__ __forceinline__ u64 add2(u64 a, u64 b) {
    u64 d; asm("add.rn.f32x2 %0,%1,%2;" : "=l"(d) : "l"(a), "l"(b)); return d;
}

// ---------------- scratch (device globals; no allocation) ----------------
__device__ float g_h[NTOK * DD];
__device__ float g_z[NTOK * DD];
__device__ float g_qkv[NTOK * 3 * DD];
__device__ float g_o[NTOK * DD];
__device__ float g_y[NASG * DD];
__device__ float g_blockSumP[512 * EE];
__device__ int   g_count[EE];
__device__ int   g_base[EE];
__device__ int   g_cursor[EE];
__device__ int   g_tok[NASG];
__device__ int   g_tope[NTOK * 2];
__device__ float g_topw[NTOK * 2];
__device__ int   g_pos[NTOK * 2];
__device__ float g_aux[1];

// 16 packed FMAs: 4 token-pairs x 4 cols
#define FMA2_4x4(acc, a01, a23, w0, w1, w2, w3)          \
    do {                                                  \
        acc[0][0] = fma2(a01.x, w0, acc[0][0]);           \
        acc[0][1] = fma2(a01.x, w1, acc[0][1]);           \
        acc[0][2] = fma2(a01.x, w2, acc[0][2]);           \
        acc[0][3] = fma2(a01.x, w3, acc[0][3]);           \
        acc[1][0] = fma2(a01.y, w0, acc[1][0]);           \
        acc[1][1] = fma2(a01.y, w1, acc[1][1]);           \
        acc[1][2] = fma2(a01.y, w2, acc[1][2]);           \
        acc[1][3] = fma2(a01.y, w3, acc[1][3]);           \
        acc[2][0] = fma2(a23.x, w0, acc[2][0]);           \
        acc[2][1] = fma2(a23.x, w1, acc[2][1]);           \
        acc[2][2] = fma2(a23.x, w2, acc[2][2]);           \
        acc[2][3] = fma2(a23.x, w3, acc[2][3]);           \
        acc[3][0] = fma2(a23.y, w0, acc[3][0]);           \
        acc[3][1] = fma2(a23.y, w1, acc[3][1]);           \
        acc[3][2] = fma2(a23.y, w2, acc[3][2]);           \
        acc[3][3] = fma2(a23.y, w3, acc[3][3]);           \
    } while (0)

// ---------------- input projection: tile 32 tok x 128 col, thread 4x4 ----------------
__global__ __launch_bounds__(256) void k_proj(const float* __restrict__ x,
                                              const float* __restrict__ W,
                                              const float* __restrict__ bias,
                                              const float* __restrict__ pos) {
    extern __shared__ float AsT[];  // [INJ][36] = 63360 B
    int t0 = blockIdx.x * 32;
    for (int idx = threadIdx.x; idx < 32 * INJ; idx += 256) {
        int i = idx / INJ, j = idx - i * INJ;
        int tok = t0 + i;
        int b = tok >> 9, t = tok & 511;
        AsT[j * 36 + i] = x[(((b * NBC + j / NCC) * TT + t) * NCC) + (j % NCC)];
    }
    __syncthreads();
    int lane = threadIdx.x & 31, wrp = threadIdx.x >> 5;  // wrp: 8 groups x 4 tokens
    int col = lane * 4;
    const float4* W4 = (const float4*)W;
    u64 acc[2][4] = {};
#pragma unroll 4
    for (int j = 0; j < INJ; j++) {
        ulonglong2 a01 = *(const ulonglong2*)(AsT + j * 36 + wrp * 4);
        float4 w = W4[j * 32 + (col >> 2)];
        u64 w0 = pk2(w.x), w1 = pk2(w.y), w2 = pk2(w.z), w3 = pk2(w.w);
        acc[0][0] = fma2(a01.x, w0, acc[0][0]);
        acc[0][1] = fma2(a01.x, w1, acc[0][1]);
        acc[0][2] = fma2(a01.x, w2, acc[0][2]);
        acc[0][3] = fma2(a01.x, w3, acc[0][3]);
        acc[1][0] = fma2(a01.y, w0, acc[1][0]);
        acc[1][1] = fma2(a01.y, w1, acc[1][1]);
        acc[1][2] = fma2(a01.y, w2, acc[1][2]);
        acc[1][3] = fma2(a01.y, w3, acc[1][3]);
    }
    float4 b4 = ((const float4*)bias)[col >> 2];
#pragma unroll
    for (int p = 0; p < 2; p++) {
        float2 u0 = up2(acc[p][0]), u1 = up2(acc[p][1]);
        float2 u2 = up2(acc[p][2]), u3 = up2(acc[p][3]);
        int tokA = t0 + wrp * 4 + 2 * p;
        int tA = tokA & 511, tB = (tokA + 1) & 511;
        float4 pA = ((const float4*)pos)[tA * 32 + (col >> 2)];
        float4 pB = ((const float4*)pos)[tB * 32 + (col >> 2)];
        *(float4*)(g_h + tokA * DD + col) =
            make_float4(u0.x + b4.x + pA.x, u1.x + b4.y + pA.y,
                        u2.x + b4.z + pA.z, u3.x + b4.w + pA.w);
        *(float4*)(g_h + (tokA + 1) * DD + col) =
            make_float4(u0.y + b4.x + pB.x, u1.y + b4.y + pB.y,
                        u2.y + b4.z + pB.z, u3.y + b4.w + pB.w);
    }
}

// ---------------- LayerNorm: g_h -> g_z (warp per token) ----------------
__global__ void k_ln(const float* __restrict__ gam, const float* __restrict__ bet) {
    int warp = (blockIdx.x * blockDim.x + threadIdx.x) >> 5;
    int lane = threadIdx.x & 31;
    if (warp >= NTOK) return;
    const float* xr = g_h + warp * DD;
    float v[4];
    float s = 0.f;
#pragma unroll
    for (int j = 0; j < 4; j++) { v[j] = xr[lane + j * 32]; s += v[j]; }
#pragma unroll
    for (int o = 16; o; o >>= 1) s += __shfl_xor_sync(0xffffffffu, s, o);
    float m = s * (1.0f / DD);
    float q = 0.f;
#pragma unroll
    for (int j = 0; j < 4; j++) { float dv = v[j] - m; q += dv * dv; }
#pragma unroll
    for (int o = 16; o; o >>= 1) q += __shfl_xor_sync(0xffffffffu, q, o);
    float r = rsqrtf(q * (1.0f / DD) + 1e-5f);
#pragma unroll
    for (int j = 0; j < 4; j++) {
        int d = lane + j * 32;
        g_z[warp * DD + d] = (v[j] - m) * r * gam[d] + bet[d];
    }
}

// ---------------- qkv GEMM: tile 64 tok x 128 col, thread 8x4 ----------------
__global__ __launch_bounds__(256) void k_gemm_qkv(const float* __restrict__ W,
                                                  const float* __restrict__ bias) {
    __shared__ float AsT[DD * 68];  // [k][64 tok + pad] = 34816 B
    int t0 = blockIdx.x * 64;
    for (int idx = threadIdx.x; idx < 64 * DD; idx += 256) {
        int i = idx >> 7, d = idx & 127;
        AsT[d * 68 + i] = g_z[(t0 + i) * DD + d];
    }
    __syncthreads();
    int lane = threadIdx.x & 31, wrp = threadIdx.x >> 5;
    int trow = wrp * 8;
    int col = blockIdx.y * 128 + lane * 4;
    const float4* W4 = (const float4*)W;
    u64 acc[4][4] = {};
#pragma unroll 4
    for (int k = 0; k < DD; k++) {
        ulonglong2 a01 = *(const ulonglong2*)(AsT + k * 68 + trow);
        ulonglong2 a23 = *(const ulonglong2*)(AsT + k * 68 + trow + 4);
        float4 w = W4[k * 96 + (col >> 2)];
        u64 w0 = pk2(w.x), w1 = pk2(w.y), w2 = pk2(w.z), w3 = pk2(w.w);
        FMA2_4x4(acc, a01, a23, w0, w1, w2, w3);
    }
    float4 b4 = ((const float4*)bias)[col >> 2];
#pragma unroll
    for (int p = 0; p < 4; p++) {
        float2 u0 = up2(acc[p][0]), u1 = up2(acc[p][1]);
        float2 u2 = up2(acc[p][2]), u3 = up2(acc[p][3]);
        int row = t0 + trow + 2 * p;
        *(float4*)(g_qkv + row * 384 + col) =
            make_float4(u0.x + b4.x, u1.x + b4.y, u2.x + b4.z, u3.x + b4.w);
        *(float4*)(g_qkv + (row + 1) * 384 + col) =
            make_float4(u0.y + b4.x, u1.y + b4.y, u2.y + b4.z, u3.y + b4.w);
    }
}

// ---------------- attention: block per (b,h), 2 rows/thread, packed f32x2 ----------------
__global__ __launch_bounds__(256) void k_attn() {
    extern __shared__ float sm[];
    float* Ks = sm;
    float* Vs = sm + TT * DHH;
    int b = blockIdx.x >> 3, hh = blockIdx.x & 7;
    const float* base = g_qkv + (b * TT) * 384;
    for (int idx = threadIdx.x; idx < TT * DHH; idx += 256) {
        int k = idx >> 4, d = idx & 15;
        Ks[idx] = base[k * 384 + 128 + hh * 16 + d];
        Vs[idx] = base[k * 384 + 256 + hh * 16 + d];
    }
    __syncthreads();
    int r0 = threadIdx.x, r1 = threadIdx.x + 256;
    u64 q0[8], q1[8], o0[8] = {}, o1[8] = {};
    {
        const ulonglong2* qp0 = (const ulonglong2*)(base + r0 * 384 + hh * 16);
        const ulonglong2* qp1 = (const ulonglong2*)(base + r1 * 384 + hh * 16);
        u64 sc = pk2(0.25f);
#pragma unroll
        for (int j = 0; j < 4; j++) {
            ulonglong2 t = qp0[j];
            q0[2 * j] = mul2(t.x, sc); q0[2 * j + 1] = mul2(t.y, sc);
            t = qp1[j];
            q1[2 * j] = mul2(t.x, sc); q1[2 * j + 1] = mul2(t.y, sc);
        }
    }
    float m0 = -1e30f, l0 = 0.f, m1 = -1e30f, l1 = 0.f;
#pragma unroll 1
    for (int k = 0; k < TT; k++) {
        const ulonglong2* kp = (const ulonglong2*)(Ks + k * 16);
        u64 kk[8];
#pragma unroll
        for (int j = 0; j < 4; j++) { ulonglong2 t = kp[j]; kk[2 * j] = t.x; kk[2 * j + 1] = t.y; }
        u64 sa = mul2(q0[0], kk[0]), sb = mul2(q0[1], kk[1]);
        sa = fma2(q0[2], kk[2], sa); sb = fma2(q0[3], kk[3], sb);
        sa = fma2(q0[4], kk[4], sa); sb = fma2(q0[5], kk[5], sb);
        sa = fma2(q0[6], kk[6], sa); sb = fma2(q0[7], kk[7], sb);
        float2 sr = up2(add2(sa, sb));
        float s0v = sr.x + sr.y;
        sa = mul2(q1[0], kk[0]); sb = mul2(q1[1], kk[1]);
        sa = fma2(q1[2], kk[2], sa); sb = fma2(q1[3], kk[3], sb);
        sa = fma2(q1[4], kk[4], sa); sb = fma2(q1[5], kk[5], sb);
        sa = fma2(q1[6], kk[6], sa); sb = fma2(q1[7], kk[7], sb);
        sr = up2(add2(sa, sb));
        float s1v = sr.x + sr.y;
        const ulonglong2* vp = (const ulonglong2*)(Vs + k * 16);
        u64 vv[8];
#pragma unroll
        for (int j = 0; j < 4; j++) { ulonglong2 t = vp[j]; vv[2 * j] = t.x; vv[2 * j + 1] = t.y; }
        if (s0v > m0) {
            float f = __expf(m0 - s0v);
            l0 *= f;
            u64 fp = pk2(f);
#pragma unroll
            for (int j = 0; j < 8; j++) o0[j] = mul2(o0[j], fp);
            m0 = s0v;
        }
        float p0 = __expf(s0v - m0);
        l0 += p0;
        u64 pp0 = pk2(p0);
#pragma unroll
        for (int j = 0; j < 8; j++) o0[j] = fma2(pp0, vv[j], o0[j]);
        if (s1v > m1) {
            float f = __expf(m1 - s1v);
            l1 *= f;
            u64 fp = pk2(f);
#pragma unroll
            for (int j = 0; j < 8; j++) o1[j] = mul2(o1[j], fp);
            m1 = s1v;
        }
        float p1 = __expf(s1v - m1);
        l1 += p1;
        u64 pp1 = pk2(p1);
#pragma unroll
        for (int j = 0; j < 8; j++) o1[j] = fma2(pp1, vv[j], o1[j]);
    }
    float inv0 = 1.f / l0, inv1 = 1.f / l1;
    float4* op0 = (float4*)(g_o + (b * TT + r0) * DD + hh * 16);
    float4* op1 = (float4*)(g_o + (b * TT + r1) * DD + hh * 16);
#pragma unroll
    for (int j = 0; j < 4; j++) {
        float2 a = up2(o0[2 * j]), c = up2(o0[2 * j + 1]);
        op0[j] = make_float4(a.x * inv0, a.y * inv0, c.x * inv0, c.y * inv0);
        a = up2(o1[2 * j]); c = up2(o1[2 * j + 1]);
        op1[j] = make_float4(a.x * inv1, a.y * inv1, c.x * inv1, c.y * inv1);
    }
}

// ---------------- out proj GEMM + residual ----------------
__global__ __launch_bounds__(256) void k_gemm_out(const float* __restrict__ W,
                                                  const float* __restrict__ bias) {
    __shared__ float AsT[DD * 68];
    int t0 = blockIdx.x * 64;
    for (int idx = threadIdx.x; idx < 64 * DD; idx += 256) {
        int i = idx >> 7, d = idx & 127;
        AsT[d * 68 + i] = g_o[(t0 + i) * DD + d];
    }
    __syncthreads();
    int lane = threadIdx.x & 31, wrp = threadIdx.x >> 5;
    int trow = wrp * 8;
    int col = lane * 4;
    const float4* W4 = (const float4*)W;
    u64 acc[4][4] = {};
#pragma unroll 4
    for (int k = 0; k < DD; k++) {
        ulonglong2 a01 = *(const ulonglong2*)(AsT + k * 68 + trow);
        ulonglong2 a23 = *(const ulonglong2*)(AsT + k * 68 + trow + 4);
        float4 w = W4[k * 32 + (col >> 2)];
        u64 w0 = pk2(w.x), w1 = pk2(w.y), w2 = pk2(w.z), w3 = pk2(w.w);
        FMA2_4x4(acc, a01, a23, w0, w1, w2, w3);
    }
    float4 b4 = ((const float4*)bias)[col >> 2];
#pragma unroll
    for (int p = 0; p < 4; p++) {
        float2 u0 = up2(acc[p][0]), u1 = up2(acc[p][1]);
        float2 u2 = up2(acc[p][2]), u3 = up2(acc[p][3]);
        int row = t0 + trow + 2 * p;
        float4* hp = (float4*)(g_h + row * DD + col);
        float4 h0 = hp[0];
        hp[0] = make_float4(h0.x + u0.x + b4.x, h0.y + u1.x + b4.y,
                            h0.z + u2.x + b4.z, h0.w + u3.x + b4.w);
        float4* hp1 = (float4*)(g_h + (row + 1) * DD + col);
        float4 h1 = hp1[0];
        hp1[0] = make_float4(h1.x + u0.y + b4.x, h1.y + u1.y + b4.y,
                             h1.z + u2.y + b4.z, h1.w + u3.y + b4.w);
    }
}

// ---------------- gate: logits, softmax, top-2, counts, per-block prob sums ----------------
__global__ void k_zero_gate() {
    if (threadIdx.x < EE) g_count[threadIdx.x] = 0;
}

__global__ void k_gate(const float* __restrict__ gW) {
    __shared__ float zs[32 * DD];
    __shared__ float gw[DD * EE];
    __shared__ float lg[32 * EE];
    __shared__ float sp[32 * EE];
    int t0 = blockIdx.x * 32;
    for (int idx = threadIdx.x; idx < 32 * DD; idx += 256) zs[idx] = g_z[t0 * DD + idx];
    for (int idx = threadIdx.x; idx < DD * EE; idx += 256) gw[idx] = gW[idx];
    __syncthreads();
    {
        int tok = threadIdx.x >> 3, e = threadIdx.x & 7;
        float acc = 0.f;
        for (int k = 0; k < DD; k++) acc += zs[tok * DD + k] * gw[k * EE + e];
        lg[tok * EE + e] = acc;
    }
    __syncthreads();
    if (threadIdx.x < 32) {
        int tt = threadIdx.x;
        float mx = -1e30f;
#pragma unroll
        for (int j = 0; j < 8; j++) mx = fmaxf(mx, lg[tt * 8 + j]);
        float p[8];
        float s = 0.f;
#pragma unroll
        for (int j = 0; j < 8; j++) { p[j] = __expf(lg[tt * 8 + j] - mx); s += p[j]; }
        float invs = 1.f / s;
#pragma unroll
        for (int j = 0; j < 8; j++) p[j] *= invs;
        int i1 = 0; float l1 = lg[tt * 8];
        for (int j = 1; j < 8; j++) if (lg[tt * 8 + j] > l1) { l1 = lg[tt * 8 + j]; i1 = j; }
        int i2 = -1; float l2 = -1e30f;
        for (int j = 0; j < 8; j++)
            if (j != i1 && lg[tt * 8 + j] > l2) { l2 = lg[tt * 8 + j]; i2 = j; }
        float v1 = p[i1], v2 = p[i2];
        float ws = 1.f / (v1 + v2);
        int t = t0 + tt;
        g_tope[t * 2] = i1; g_tope[t * 2 + 1] = i2;
        g_topw[t * 2] = v1 * ws; g_topw[t * 2 + 1] = v2 * ws;
        atomicAdd(&g_count[i1], 1);
        atomicAdd(&g_count[i2], 1);
#pragma unroll
        for (int j = 0; j < 8; j++) sp[tt * 8 + j] = p[j];
    }
    __syncthreads();
    if (threadIdx.x < 8) {
        float s = 0.f;
        for (int tt = 0; tt < 32; tt++) s += sp[tt * 8 + threadIdx.x];
        g_blockSumP[blockIdx.x * 8 + threadIdx.x] = s;
    }
}

// ---------------- scan bases + deterministic aux accumulation ----------------
__global__ void k_scan_aux() {
    __shared__ float sump[8];
    int tid = threadIdx.x;
    if (tid < 8) {
        float s = 0.f;
        for (int b = 0; b < 512; b++) s += g_blockSumP[b * 8 + tid];
        sump[tid] = s;
    }
    __syncthreads();
    if (tid == 0) {
        int off = 0;
        float a = 0.f;
        for (int e = 0; e < 8; e++) {
            g_base[e] = off;
            g_cursor[e] = off;
            off += g_count[e];
            a += sump[e] * (float)g_count[e];
        }
        g_aux[0] += 8.0f * a / (16384.f * 16384.f);
    }
}

// ---------------- assignment (block-aggregated atomics) ----------------
__global__ void k_assign() {
    __shared__ int cnt[8], gbase[8];
    int tid = threadIdx.x;
    if (tid < 8) cnt[tid] = 0;
    __syncthreads();
    int t = blockIdx.x * 256 + tid;
    int e0 = g_tope[t * 2], e1 = g_tope[t * 2 + 1];
    int o0 = atomicAdd(&cnt[e0], 1);
    int o1 = atomicAdd(&cnt[e1], 1);
    __syncthreads();
    if (tid < 8) gbase[tid] = atomicAdd(&g_cursor[tid], cnt[tid]);
    __syncthreads();
    int p0 = gbase[e0] + o0, p1 = gbase[e1] + o1;
    g_tok[p0] = t; g_tok[p1] = t;
    g_pos[t * 2] = p0; g_pos[t * 2 + 1] = p1;
}

// ---------------- grouped expert FFN ----------------
__global__ __launch_bounds__(256) void k_ffn(const float* __restrict__ w1,
                                             const float* __restrict__ b1,
                                             const float* __restrict__ w2,
                                             const float* __restrict__ b2) {
    int e = blockIdx.y;
    int n = g_count[e];
    int start = blockIdx.x * 32;
    if (start >= n) return;
    int base = g_base[e];
    extern __shared__ float sm[];
    float* zsT = sm;                // [128][36] = 18432 B
    float* hidT = sm + DD * 36;     // [512][36] = 73728 B
    __shared__ int toks[32];
    int tid = threadIdx.x;
    if (tid < 32) toks[tid] = (start + tid < n) ? g_tok[base + start + tid] : -1;
    __syncthreads();
    for (int idx = tid; idx < 32 * DD; idx += 256) {
        int i = idx >> 7, d = idx & 127;
        int tk = toks[i];
        zsT[d * 36 + i] = (tk >= 0) ? g_z[tk * DD + d] : 0.f;
    }
    __syncthreads();
    const float* W1 = w1 + e * DD * FFH;
    const float* B1 = b1 + e * FFH;
    const float4* W1_4 = (const float4*)W1;
    int tg = tid >> 6;              // 4 groups x 8 tokens
#pragma unroll 1
    for (int pp = 0; pp < 2; pp++) {
        int f = pp * 256 + (tid & 63) * 4;
        u64 acc[4][4] = {};
#pragma unroll 2
        for (int d = 0; d < DD; d++) {
            ulonglong2 a01 = *(const ulonglong2*)(zsT + d * 36 + tg * 8);
            ulonglong2 a23 = *(const ulonglong2*)(zsT + d * 36 + tg * 8 + 4);
            float4 w = W1_4[d * 128 + (f >> 2)];
            u64 w0 = pk2(w.x), w1v = pk2(w.y), w2v = pk2(w.z), w3 = pk2(w.w);
            FMA2_4x4(acc, a01, a23, w0, w1v, w2v, w3);
        }
        float4 bb = ((const float4*)B1)[f >> 2];
        float v[8][4];
#pragma unroll
        for (int p = 0; p < 4; p++) {
            float2 u0 = up2(acc[p][0]), u1 = up2(acc[p][1]);
            float2 u2 = up2(acc[p][2]), u3 = up2(acc[p][3]);
            v[2 * p][0] = u0.x + bb.x; v[2 * p][1] = u1.x + bb.y;
            v[2 * p][2] = u2.x + bb.z; v[2 * p][3] = u3.x + bb.w;
            v[2 * p + 1][0] = u0.y + bb.x; v[2 * p + 1][1] = u1.y + bb.y;
            v[2 * p + 1][2] = u2.y + bb.z; v[2 * p + 1][3] = u3.y + bb.w;
        }
#pragma unroll
        for (int i = 0; i < 8; i++)
#pragma unroll
            for (int j = 0; j < 4; j++) {
                float xv = v[i][j];
                float t = tanhf(0.7978845608028654f * (xv + 0.044715f * xv * xv * xv));
                v[i][j] = 0.5f * xv * (1.f + t);
            }
#pragma unroll
        for (int j = 0; j < 4; j++) {
            *(float4*)(hidT + (f + j) * 36 + tg * 8) =
                make_float4(v[0][j], v[1][j], v[2][j], v[3][j]);
            *(float4*)(hidT + (f + j) * 36 + tg * 8 + 4) =
                make_float4(v[4][j], v[5][j], v[6][j], v[7][j]);
        }
    }
    __syncthreads();
    const float* W2 = w2 + e * FFH * DD;
    const float* B2 = b2 + e * DD;
    const float4* W2_4 = (const float4*)W2;
    int tg2 = tid >> 5;             // 8 groups x 4 tokens
    int d = (tid & 31) * 4;
    u64 acc2[2][4] = {};
#pragma unroll 4
    for (int f = 0; f < FFH; f++) {
        ulonglong2 h01 = *(const ulonglong2*)(hidT + f * 36 + tg2 * 4);
        float4 w = W2_4[f * 32 + (d >> 2)];
        u64 w0 = pk2(w.x), w1v = pk2(w.y), w2v = pk2(w.z), w3 = pk2(w.w);
        acc2[0][0] = fma2(h01.x, w0, acc2[0][0]);
        acc2[0][1] = fma2(h01.x, w1v, acc2[0][1]);
        acc2[0][2] = fma2(h01.x, w2v, acc2[0][2]);
        acc2[0][3] = fma2(h01.x, w3, acc2[0][3]);
        acc2[1][0] = fma2(h01.y, w0, acc2[1][0]);
        acc2[1][1] = fma2(h01.y, w1v, acc2[1][1]);
        acc2[1][2] = fma2(h01.y, w2v, acc2[1][2]);
        acc2[1][3] = fma2(h01.y, w3, acc2[1][3]);
    }
    float4 b4 = ((const float4*)B2)[d >> 2];
#pragma unroll
    for (int p = 0; p < 2; p++) {
        float2 u0 = up2(acc2[p][0]), u1 = up2(acc2[p][1]);
        float2 u2 = up2(acc2[p][2]), u3 = up2(acc2[p][3]);
        int a0 = start + tg2 * 4 + 2 * p;
        if (a0 < n)
            *(float4*)(g_y + (base + a0) * DD + d) =
                make_float4(u0.x + b4.x, u1.x + b4.y, u2.x + b4.z, u3.x + b4.w);
        if (a0 + 1 < n)
            *(float4*)(g_y + (base + a0 + 1) * DD + d) =
                make_float4(u0.y + b4.x, u1.y + b4.y, u2.y + b4.z, u3.y + b4.w);
    }
}

// ---------------- combine: h += w0*y[pos0] + w1*y[pos1] ----------------
__global__ void k_combine() {
    int idx = blockIdx.x * 256 + threadIdx.x;
    int t = idx >> 7, d = idx & 127;
    float w0 = g_topw[t * 2], w1v = g_topw[t * 2 + 1];
    int p0 = g_pos[t * 2], p1 = g_pos[t * 2 + 1];
    g_h[idx] += w0 * g_y[p0 * DD + d] + w1v * g_y[p1 * DD + d];
}

// ---------------- head: mean-pool, LN, [128,2] GEMV, aux writeout ----------------
__global__ void k_head(const float* __restrict__ lng, const float* __restrict__ lnb,
                       const float* __restrict__ hW, const float* __restrict__ hb,
                       float* __restrict__ out, int out_size) {
    __shared__ float red[128];
    int b = blockIdx.x, d = threadIdx.x;
    float s = 0.f;
    for (int t = 0; t < TT; t++) s += g_h[(b * TT + t) * DD + d];
    float x = s * (1.f / TT);
    red[d] = x;
    __syncthreads();
    for (int o = 64; o; o >>= 1) { if (d < o) red[d] += red[d + o]; __syncthreads(); }
    float m = red[0] * (1.f / DD);
    __syncthreads();
    float dv = x - m;
    red[d] = dv * dv;
    __syncthreads();
    for (int o = 64; o; o >>= 1) { if (d < o) red[d] += red[d + o]; __syncthreads(); }
    float var = red[0] * (1.f / DD);
    __syncthreads();
    float p = dv * rsqrtf(var + 1e-5f) * lng[d] + lnb[d];
#pragma unroll 1
    for (int j = 0; j < 2; j++) {
        red[d] = p * hW[d * 2 + j];
        __syncthreads();
        for (int o = 64; o; o >>= 1) { if (d < o) red[d] += red[d + o]; __syncthreads(); }
        if (d == 0) out[b * 2 + j] = red[0] + hb[j];
        __syncthreads();
    }
    if (b == 0 && d == 0 && out_size > 64) out[64] = g_aux[0];
}

__global__ void k_zero_aux() {
    if (threadIdx.x == 0) g_aux[0] = 0.f;
}

// ---------------- host launch ----------------
extern "C" void kernel_launch(void* const* d_in, const int* in_sizes, int n_in,
                              void* d_out, int out_size) {
    const float* x     = (const float*)d_in[0];
    const float* projW = (const float*)d_in[1];
    const float* projb = (const float*)d_in[2];
    const float* pos   = (const float*)d_in[3];
    const float* ln1g  = (const float*)d_in[4];
    const float* ln1b  = (const float*)d_in[5];
    const float* qkvW  = (const float*)d_in[6];
    const float* qkvb  = (const float*)d_in[7];
    const float* outW  = (const float*)d_in[8];
    const float* outb  = (const float*)d_in[9];
    const float* ln2g  = (const float*)d_in[10];
    const float* ln2b  = (const float*)d_in[11];
    const float* gateW = (const float*)d_in[12];
    const float* w1    = (const float*)d_in[13];
    const float* b1    = (const float*)d_in[14];
    const float* w2    = (const float*)d_in[15];
    const float* b2    = (const float*)d_in[16];
    const float* hlng  = (const float*)d_in[17];
    const float* hlnb  = (const float*)d_in[18];
    const float* hW    = (const float*)d_in[19];
    const float* hb    = (const float*)d_in[20];
    float* out = (float*)d_out;

    cudaFuncSetAttribute(k_attn, cudaFuncAttributeMaxDynamicSharedMemorySize, 65536);
    cudaFuncSetAttribute(k_ffn, cudaFuncAttributeMaxDynamicSharedMemorySize,
                         (DD + FFH) * 36 * 4);
    cudaFuncSetAttribute(k_proj, cudaFuncAttributeMaxDynamicSharedMemorySize, INJ * 36 * 4);

    k_zero_aux<<<1, 32>>>();
    k_proj<<<NTOK / 32, 256, INJ * 36 * 4>>>(x, projW, projb, pos);

    for (int i = 0; i < DEPTH_; i++) {
        k_ln<<<NTOK / 8, 256>>>(ln1g + i * DD, ln1b + i * DD);
        k_gemm_qkv<<<dim3(NTOK / 64, 3), 256>>>(qkvW + i * DD * 384, qkvb + i * 384);
        k_attn<<<BB * HH, 256, 65536>>>();
        k_gemm_out<<<NTOK / 64, 256>>>(outW + i * DD * DD, outb + i * DD);
        k_ln<<<NTOK / 8, 256>>>(ln2g + i * DD, ln2b + i * DD);
        k_zero_gate<<<1, 32>>>();
        k_gate<<<NTOK / 32, 256>>>(gateW + i * DD * EE);
        k_scan_aux<<<1, 32>>>();
        k_assign<<<NTOK / 256, 256>>>();
        k_ffn<<<dim3(NASG / 32, EE), 256, (DD + FFH) * 36 * 4>>>(
            w1 + i * EE * DD * FFH, b1 + i * EE * FFH,
            w2 + i * EE * FFH * DD, b2 + i * EE * DD);
        k_combine<<<NTOK * DD / 256, 256>>>();
    }

    k_head<<<BB, 128>>>(hlng, hlnb, hW, hb, out, out_size);
}